// round 14
// baseline (speedup 1.0000x reference)
#include <cuda_runtime.h>
#include <cuda_fp16.h>
#include <cstdint>

#define MAXN 100000
#define MAXE 1600000
#define EPS_LN 1e-5f

typedef unsigned long long u64;
typedef unsigned int u32;

// ---------------- scratch (device globals; zero-initialized at load) -------
__device__ int    g_degi[MAXN];            // must be 0 at entry; re-zeroed at end
__device__ int    g_off[MAXN + 1];
__device__ int    g_cursor[MAXN];
__device__ int    g_csr[MAXE];
__device__ float  g_rdeg[MAXN];
__device__ __half g_xh[(size_t)MAXN * 128];
__device__ __half g_h0h[(size_t)MAXN * 128];
__device__ __half g_h1h[(size_t)MAXN * 128];
__device__ float  g_t2lo[(size_t)MAXN * 64];   // fp32 logits part (cols 0-63)
__device__ __half g_t2hi[(size_t)MAXN * 64];   // fp16 gathered part (cols 64-127)
__device__ __half g_Bw0h[128 * 256];   // [n][k] half weights (concat, transposed)
__device__ __half g_Bw1h[128 * 256];
__device__ __half g_Bw2h[128 * 128];

// ---------------- helpers ---------------------------------------------------
__device__ __forceinline__ uint32_t smem_u32(const void* p) {
    uint32_t a;
    asm("{ .reg .u64 t; cvta.to.shared.u64 t, %1; cvt.u32.u64 %0, t; }" : "=r"(a) : "l"(p));
    return a;
}
__device__ __forceinline__ void cp_async16(uint32_t dst, const void* src) {
    asm volatile("cp.async.ca.shared.global [%0], [%1], 16;" :: "r"(dst), "l"(src));
}
__device__ __forceinline__ void cp_commit() {
    asm volatile("cp.async.commit_group;" ::: "memory");
}
__device__ __forceinline__ void cp_wait0() {
    asm volatile("cp.async.wait_group 0;" ::: "memory");
}
__device__ __forceinline__ void mma_f16(float* c, const u32* a, u32 b0, u32 b1) {
    asm volatile(
        "mma.sync.aligned.m16n8k16.row.col.f32.f16.f16.f32 "
        "{%0,%1,%2,%3}, {%4,%5,%6,%7}, {%8,%9}, {%0,%1,%2,%3};"
        : "+f"(c[0]), "+f"(c[1]), "+f"(c[2]), "+f"(c[3])
        : "r"(a[0]), "r"(a[1]), "r"(a[2]), "r"(a[3]), "r"(b0), "r"(b1));
}
__device__ __forceinline__ float4 ldg4(const float* p) {
    return __ldg(reinterpret_cast<const float4*>(p));
}
__device__ __forceinline__ void acc_h4(float4& a, uint2 p) {
    float2 lo = __half22float2(*reinterpret_cast<__half2*>(&p.x));
    float2 hi = __half22float2(*reinterpret_cast<__half2*>(&p.y));
    a.x += lo.x; a.y += lo.y; a.z += hi.x; a.w += hi.y;
}
__device__ __forceinline__ uint2 f4_to_h4(float4 v) {
    uint2 r;
    __half2 lo = __floats2half2_rn(v.x, v.y);
    __half2 hi = __floats2half2_rn(v.z, v.w);
    r.x = *reinterpret_cast<u32*>(&lo);
    r.y = *reinterpret_cast<u32*>(&hi);
    return r;
}

// ---------------- CSR build --------------------------------------------------
__global__ void k_zeroi(int* __restrict__ p, int n) {
    int i = blockIdx.x * blockDim.x + threadIdx.x;
    if (i < n) p[i] = 0;
}

__global__ void k_count(const int* __restrict__ dst, int* __restrict__ deg, int E) {
    int i = blockIdx.x * blockDim.x + threadIdx.x;
    if (i < E) atomicAdd(&deg[dst[i]], 1);
}

__global__ void __launch_bounds__(1024) k_scan(
    const int* __restrict__ deg, int* __restrict__ off,
    int* __restrict__ cursor, float* __restrict__ rdeg, int n)
{
    __shared__ int sb[1024];
    int tid = threadIdx.x;
    int chunk = (n + 1023) >> 10;
    int s = tid * chunk;
    int e = min(s + chunk, n);
    int sum = 0;
    for (int i = s; i < e; i++) sum += deg[i];
    sb[tid] = sum;
    __syncthreads();
    int val = sum;
    for (int o = 1; o < 1024; o <<= 1) {
        int t = (tid >= o) ? sb[tid - o] : 0;
        __syncthreads();
        sb[tid] += t;
        __syncthreads();
    }
    int base = sb[tid] - val;
    for (int i = s; i < e; i++) {
        int d = deg[i];
        off[i] = base;
        cursor[i] = base;
        rdeg[i] = 1.0f / fmaxf((float)d, 1.0f);
        base += d;
    }
    if (tid == 1023) off[n] = base;
}

// ---------------- fused: CSR fill + weight prep + x->half ------------------
__global__ void k_fill_plus(
    const int* __restrict__ src, const int* __restrict__ dst,
    int* __restrict__ cursor, int* __restrict__ csr, int E, int FB,
    const float* __restrict__ Wr0, const float* __restrict__ Wn0,
    const float* __restrict__ Wr1, const float* __restrict__ Wn1,
    const float* __restrict__ Wr2, const float* __restrict__ Wn2,
    __half* __restrict__ B0, __half* __restrict__ B1, __half* __restrict__ B2,
    const float* __restrict__ x, __half* __restrict__ xh, long n4)
{
    int b = blockIdx.x;
    int tid = threadIdx.x;
    if (b < FB) {
        int i = b * 256 + tid;
        if (i < E) {
            int p = atomicAdd(&cursor[dst[i]], 1);
            csr[p] = src[i];
        }
    } else if (b < FB + 320) {
        int bb = b - FB;
        if (bb < 256) {
            const float* Wr = (bb < 128) ? Wr0 : Wr1;
            const float* Wn = (bb < 128) ? Wn0 : Wn1;
            __half* B = (bb < 128) ? B0 : B1;
            int i = (bb & 127) * 256 + tid;     // i = n*256 + k
            int nn = i >> 8, k = i & 255;
            float v = (k < 128) ? Wr[k * 128 + nn] : Wn[(k - 128) * 128 + nn];
            B[i] = __float2half_rn(v);
        } else {
            int i = (bb - 256) * 256 + tid;     // i = n*128 + k
            int nn = i >> 7, k = i & 127;
            float v = (nn < 64) ? Wr2[k * 64 + nn] : Wn2[k * 64 + (nn - 64)];
            B2[i] = __float2half_rn(v);
        }
    } else {
        long i = (long)(b - FB - 320) * 256 + tid;
        for (; i < n4; i += 1024L * 256) {
            float4 v = reinterpret_cast<const float4*>(x)[i];
            reinterpret_cast<uint2*>(xh)[i] = f4_to_h4(v);
        }
    }
}

// ============ FUSED gather + fp16 GEMM + bias/LN/ReLU (layers 0/1) ==========
// K = 256: chunks 0-3 stream X via cp.async; chunks 4-7 read the agg tile
// gathered into smem by phase 1. CTA 128x128, 8 warps, 80-B smem row stride
// (stride MUST be 16-byte multiple for cp.async16 destinations).
#define FS_X0   0
#define FS_X1   10240
#define FS_AGG  20480      // 4 chunk buffers x 10240 = 40960 (ends 61440)
#define FS_B0   61440
#define FS_B1   71680      // ends 81920
#define FS_SROW 0          // 128 x 132 floats = 67584 (epilogue only)
#define FS_BIAS 81920
#define FS_GAM  82432
#define FS_BET  82944
#define FS_MU   83456
#define FS_RS   83968
#define FS_TOTAL 84480

__global__ void __launch_bounds__(256) k_gemm_fused(
    const __half* __restrict__ X, const int* __restrict__ csr,
    const int* __restrict__ off, const float* __restrict__ rdeg,
    const __half* __restrict__ Bw, const float* __restrict__ bias,
    const float* __restrict__ gamma, const float* __restrict__ beta,
    __half* __restrict__ outh, int n)
{
    extern __shared__ char sm[];
    float* sbias = (float*)(sm + FS_BIAS);
    float* sgam  = (float*)(sm + FS_GAM);
    float* sbet  = (float*)(sm + FS_BET);
    float* smu   = (float*)(sm + FS_MU);
    float* srs   = (float*)(sm + FS_RS);
    float* srow  = (float*)(sm + FS_SROW);

    int tid = threadIdx.x;
    int wid = tid >> 5, lane = tid & 31;
    int g = lane >> 2, t = lane & 3;
    int wm = wid & 3, wn = wid >> 2;
    int m0 = wm * 32, n0 = wn * 64;
    int base = blockIdx.x * 128;

    if (tid < 128) {
        sbias[tid] = __ldg(bias + tid);
        sgam[tid]  = __ldg(gamma + tid);
        sbet[tid]  = __ldg(beta + tid);
    }

    auto preX = [&](int c, int st) {
        uint32_t abase = smem_u32(sm + (st ? FS_X1 : FS_X0));
        #pragma unroll
        for (int it = 0; it < 2; it++) {
            int idx = tid + it * 256;
            int row = idx >> 2, seg = idx & 3;
            int grow = base + row;
            if (grow < n)
                cp_async16(abase + (uint32_t)(row * 80 + seg * 16),
                           X + (size_t)grow * 128 + c * 32 + seg * 8);
        }
    };
    auto preB = [&](int c, int st) {
        uint32_t bbase = smem_u32(sm + (st ? FS_B1 : FS_B0));
        #pragma unroll
        for (int it = 0; it < 2; it++) {
            int idx = tid + it * 256;
            int row = idx >> 2, seg = idx & 3;
            cp_async16(bbase + (uint32_t)(row * 80 + seg * 16),
                       Bw + (size_t)row * 256 + c * 32 + seg * 8);
        }
    };

    // kick off X chunk 0, then gather the agg tile while it flies
    preX(0, 0);
    cp_commit();

    // ---- phase 1: gather mean-agg tile into FS_AGG (fp32 accum -> fp16) ----
    for (int r = wid; r < 128; r += 8) {
        int grow = base + r;
        float4 a0 = make_float4(0.f, 0.f, 0.f, 0.f);
        float4 a1 = make_float4(0.f, 0.f, 0.f, 0.f);
        float4 a2 = make_float4(0.f, 0.f, 0.f, 0.f);
        float4 a3 = make_float4(0.f, 0.f, 0.f, 0.f);
        if (grow < n) {
            int s0 = off[grow], s1 = off[grow + 1];
            int e = s0;
            for (; e + 4 <= s1; e += 4) {
                int i0 = csr[e], i1 = csr[e + 1], i2 = csr[e + 2], i3 = csr[e + 3];
                uint2 v0 = *reinterpret_cast<const uint2*>(X + (size_t)i0 * 128 + lane * 4);
                uint2 v1 = *reinterpret_cast<const uint2*>(X + (size_t)i1 * 128 + lane * 4);
                uint2 v2 = *reinterpret_cast<const uint2*>(X + (size_t)i2 * 128 + lane * 4);
                uint2 v3 = *reinterpret_cast<const uint2*>(X + (size_t)i3 * 128 + lane * 4);
                acc_h4(a0, v0); acc_h4(a1, v1); acc_h4(a2, v2); acc_h4(a3, v3);
            }
            for (; e < s1; e++) {
                int i0 = csr[e];
                uint2 v0 = *reinterpret_cast<const uint2*>(X + (size_t)i0 * 128 + lane * 4);
                acc_h4(a0, v0);
            }
            float rr = rdeg[grow];
            a0.x = ((a0.x + a1.x) + (a2.x + a3.x)) * rr;
            a0.y = ((a0.y + a1.y) + (a2.y + a3.y)) * rr;
            a0.z = ((a0.z + a1.z) + (a2.z + a3.z)) * rr;
            a0.w = ((a0.w + a1.w) + (a2.w + a3.w)) * rr;
        }
        // lane owns halves [4*lane, 4*lane+4): chunk = lane>>3, within = (lane&7)*8 B
        char* dst = sm + FS_AGG + (lane >> 3) * 10240 + r * 80 + (lane & 7) * 8;
        *reinterpret_cast<uint2*>(dst) = f4_to_h4(a0);
    }

    preB(0, 0);
    cp_commit();
    cp_wait0();
    __syncthreads();

    float acc[2][8][4];
    #pragma unroll
    for (int mt = 0; mt < 2; mt++)
        #pragma unroll
        for (int nt = 0; nt < 8; nt++)
            #pragma unroll
            for (int cc = 0; cc < 4; cc++) acc[mt][nt][cc] = 0.f;

    #pragma unroll 1
    for (int c = 0; c < 8; c++) {
        int st = c & 1;
        bool pre = (c + 1 < 8);
        if (pre) {
            if (c + 1 < 4) preX(c + 1, st ^ 1);
            preB(c + 1, st ^ 1);
            cp_commit();
        }
        {
            const char* As = (c < 4) ? (sm + (st ? FS_X1 : FS_X0))
                                     : (sm + FS_AGG + (c - 4) * 10240);
            const char* Bs = sm + (st ? FS_B1 : FS_B0);
            #pragma unroll
            for (int ks = 0; ks < 2; ks++) {
                int kb = ks * 32 + 4 * t;
                u32 af[2][4];
                #pragma unroll
                for (int mt = 0; mt < 2; mt++) {
                    int r = m0 + mt * 16 + g;
                    af[mt][0] = *(const u32*)(As + r * 80 + kb);
                    af[mt][1] = *(const u32*)(As + (r + 8) * 80 + kb);
                    af[mt][2] = *(const u32*)(As + r * 80 + kb + 16);
                    af[mt][3] = *(const u32*)(As + (r + 8) * 80 + kb + 16);
                }
                #pragma unroll
                for (int nt = 0; nt < 8; nt++) {
                    int cc = n0 + nt * 8 + g;
                    u32 b0 = *(const u32*)(Bs + cc * 80 + kb);
                    u32 b1 = *(const u32*)(Bs + cc * 80 + kb + 16);
                    mma_f16(acc[0][nt], af[0], b0, b1);
                    mma_f16(acc[1][nt], af[1], b0, b1);
                }
            }
        }
        if (pre) {
            cp_wait0();
            __syncthreads();
        }
    }
    __syncthreads();

    // fragments -> srow staging
    #pragma unroll
    for (int mt = 0; mt < 2; mt++) {
        int r0 = m0 + mt * 16 + g;
        #pragma unroll
        for (int nt = 0; nt < 8; nt++) {
            int col = n0 + nt * 8 + 2 * t;
            *reinterpret_cast<float2*>(&srow[r0 * 132 + col]) =
                make_float2(acc[mt][nt][0], acc[mt][nt][1]);
            *reinterpret_cast<float2*>(&srow[(r0 + 8) * 132 + col]) =
                make_float2(acc[mt][nt][2], acc[mt][nt][3]);
        }
    }
    __syncthreads();

    // per-row LN stats (thread = row)
    if (tid < 128) {
        float s1 = 0.f, s2 = 0.f;
        #pragma unroll
        for (int j = 0; j < 128; j += 4) {
            float4 v = *reinterpret_cast<const float4*>(&srow[tid * 132 + j]);
            v.x += sbias[j + 0]; v.y += sbias[j + 1];
            v.z += sbias[j + 2]; v.w += sbias[j + 3];
            *reinterpret_cast<float4*>(&srow[tid * 132 + j]) = v;
            s1 += (v.x + v.y) + (v.z + v.w);
            s2 += (v.x * v.x + v.y * v.y) + (v.z * v.z + v.w * v.w);
        }
        float mu = s1 * (1.0f / 128.0f);
        float var = s2 * (1.0f / 128.0f) - mu * mu;
        smu[tid] = mu;
        srs[tid] = rsqrtf(var + EPS_LN);
    }
    __syncthreads();

    // coalesced half stores
    for (int r = wid; r < 128; r += 8) {
        int row = base + r;
        if (row >= n) continue;
        float4 v = *reinterpret_cast<const float4*>(&srow[r * 132 + lane * 4]);
        float mu = smu[r], rs = srs[r];
        float4 gg = *reinterpret_cast<const float4*>(&sgam[lane * 4]);
        float4 ee = *reinterpret_cast<const float4*>(&sbet[lane * 4]);
        v.x = fmaxf((v.x - mu) * rs * gg.x + ee.x, 0.f);
        v.y = fmaxf((v.y - mu) * rs * gg.y + ee.y, 0.f);
        v.z = fmaxf((v.z - mu) * rs * gg.z + ee.z, 0.f);
        v.w = fmaxf((v.w - mu) * rs * gg.w + ee.w, 0.f);
        *reinterpret_cast<uint2*>(outh + (size_t)row * 128 + lane * 4) = f4_to_h4(v);
    }
}

// ---------------- layer-2 GEMM (K=128, split fp32/fp16 output) --------------
#define S_AS0 0
#define S_AS1 10240
#define S_BS0 20480
#define S_BS1 30720
#define S_SROW 0
#define S_TOTAL 67584

__global__ void __launch_bounds__(256) k_gemm2(
    const __half* __restrict__ X, const __half* __restrict__ Bw,
    float* __restrict__ outf, __half* __restrict__ outh, int n)
{
    extern __shared__ char sm[];
    float* srow = (float*)(sm + S_SROW);

    int tid = threadIdx.x;
    int wid = tid >> 5, lane = tid & 31;
    int g = lane >> 2, t = lane & 3;
    int wm = wid & 3, wn = wid >> 2;
    int m0 = wm * 32, n0 = wn * 64;
    int base = blockIdx.x * 128;

    auto preA = [&](int c, int st) {
        uint32_t abase = smem_u32(sm + (st ? S_AS1 : S_AS0));
        #pragma unroll
        for (int it = 0; it < 2; it++) {
            int idx = tid + it * 256;
            int row = idx >> 2, seg = idx & 3;
            int grow = base + row;
            if (grow < n)
                cp_async16(abase + (uint32_t)(row * 80 + seg * 16),
                           X + (size_t)grow * 128 + c * 32 + seg * 8);
        }
    };
    auto preB = [&](int c, int st) {
        uint32_t bbase = smem_u32(sm + (st ? S_BS1 : S_BS0));
        #pragma unroll
        for (int it = 0; it < 2; it++) {
            int idx = tid + it * 256;
            int row = idx >> 2, seg = idx & 3;
            cp_async16(bbase + (uint32_t)(row * 80 + seg * 16),
                       Bw + (size_t)row * 128 + c * 32 + seg * 8);
        }
    };

    float acc[2][8][4];
    #pragma unroll
    for (int mt = 0; mt < 2; mt++)
        #pragma unroll
        for (int nt = 0; nt < 8; nt++)
            #pragma unroll
            for (int cc = 0; cc < 4; cc++) acc[mt][nt][cc] = 0.f;

    preA(0, 0);
    preB(0, 0);
    cp_commit();
    cp_wait0();
    __syncthreads();

    #pragma unroll 1
    for (int c = 0; c < 4; c++) {
        int st = c & 1;
        if (c + 1 < 4) {
            preA(c + 1, st ^ 1);
            preB(c + 1, st ^ 1);
            cp_commit();
        }
        {
            const char* As = sm + (st ? S_AS1 : S_AS0);
            const char* Bs = sm + (st ? S_BS1 : S_BS0);
            #pragma unroll
            for (int ks = 0; ks < 2; ks++) {
                int kb = ks * 32 + 4 * t;
                u32 af[2][4];
                #pragma unroll
                for (int mt = 0; mt < 2; mt++) {
                    int r = m0 + mt * 16 + g;
                    af[mt][0] = *(const u32*)(As + r * 80 + kb);
                    af[mt][1] = *(const u32*)(As + (r + 8) * 80 + kb);
                    af[mt][2] = *(const u32*)(As + r * 80 + kb + 16);
                    af[mt][3] = *(const u32*)(As + (r + 8) * 80 + kb + 16);
                }
                #pragma unroll
                for (int nt = 0; nt < 8; nt++) {
                    int cc = n0 + nt * 8 + g;
                    u32 b0 = *(const u32*)(Bs + cc * 80 + kb);
                    u32 b1 = *(const u32*)(Bs + cc * 80 + kb + 16);
                    mma_f16(acc[0][nt], af[0], b0, b1);
                    mma_f16(acc[1][nt], af[1], b0, b1);
                }
            }
        }
        if (c + 1 < 4) {
            cp_wait0();
            __syncthreads();
        }
    }
    __syncthreads();

    #pragma unroll
    for (int mt = 0; mt < 2; mt++) {
        int r0 = m0 + mt * 16 + g;
        #pragma unroll
        for (int nt = 0; nt < 8; nt++) {
            int col = n0 + nt * 8 + 2 * t;
            *reinterpret_cast<float2*>(&srow[r0 * 132 + col]) =
                make_float2(acc[mt][nt][0], acc[mt][nt][1]);
            *reinterpret_cast<float2*>(&srow[(r0 + 8) * 132 + col]) =
                make_float2(acc[mt][nt][2], acc[mt][nt][3]);
        }
    }
    __syncthreads();

    for (int r = wid; r < 128; r += 8) {
        int row = base + r;
        if (row >= n) continue;
        float4 v = *reinterpret_cast<const float4*>(&srow[r * 132 + lane * 4]);
        if (lane < 16)
            *reinterpret_cast<float4*>(outf + (size_t)row * 64 + lane * 4) = v;
        else
            *reinterpret_cast<uint2*>(outh + (size_t)row * 64 + (lane - 16) * 4) = f4_to_h4(v);
    }
}

// fused: gather t2hi (fp16) + log_softmax(t2lo + agg + b2) -> out
__global__ void __launch_bounds__(256) k_agg64_final(
    const float* __restrict__ t2lo, const __half* __restrict__ t2hi,
    const int* __restrict__ csr, const int* __restrict__ off,
    const float* __restrict__ rdeg, const float* __restrict__ b2,
    float* __restrict__ out, int n)
{
    int w = (blockIdx.x * 256 + threadIdx.x) >> 5;
    int lane = threadIdx.x & 31;
    if (w >= n) return;
    int half = lane >> 4, l = lane & 15;
    int s0 = off[w], s1 = off[w + 1];
    float4 a = make_float4(0.f, 0.f, 0.f, 0.f);
    float4 b = make_float4(0.f, 0.f, 0.f, 0.f);
    int e = s0 + half;
    for (; e + 2 < s1; e += 4) {
        int i0 = csr[e], i1 = csr[e + 2];
        uint2 v0 = *reinterpret_cast<const uint2*>(t2hi + (size_t)i0 * 64 + l * 4);
        uint2 v1 = *reinterpret_cast<const uint2*>(t2hi + (size_t)i1 * 64 + l * 4);
        acc_h4(a, v0); acc_h4(b, v1);
    }
    if (e < s1) {
        int i0 = csr[e];
        uint2 v0 = *reinterpret_cast<const uint2*>(t2hi + (size_t)i0 * 64 + l * 4);
        acc_h4(a, v0);
    }
    a.x += b.x; a.y += b.y; a.z += b.z; a.w += b.w;
    a.x += __shfl_xor_sync(0xffffffffu, a.x, 16);
    a.y += __shfl_xor_sync(0xffffffffu, a.y, 16);
    a.z += __shfl_xor_sync(0xffffffffu, a.z, 16);
    a.w += __shfl_xor_sync(0xffffffffu, a.w, 16);
    float r = rdeg[w];
    float4 tv = ldg4(t2lo + (size_t)w * 64 + l * 4);
    float4 bb = *reinterpret_cast<const float4*>(b2 + l * 4);
    float v0 = tv.x + a.x * r + bb.x;
    float v1 = tv.y + a.y * r + bb.y;
    float v2 = tv.z + a.z * r + bb.z;
    float v3 = tv.w + a.w * r + bb.w;
    float m = fmaxf(fmaxf(v0, v1), fmaxf(v2, v3));
    #pragma unroll
    for (int o = 16; o > 0; o >>= 1)
        m = fmaxf(m, __shfl_xor_sync(0xffffffffu, m, o));
    float se = (half == 0) ? (expf(v0 - m) + expf(v1 - m) + expf(v2 - m) + expf(v3 - m)) : 0.f;
    #pragma unroll
    for (int o = 16; o > 0; o >>= 1)
        se += __shfl_xor_sync(0xffffffffu, se, o);
    float ls = m + logf(se);
    if (half == 0) {
        float4 o4 = make_float4(v0 - ls, v1 - ls, v2 - ls, v3 - ls);
        *reinterpret_cast<float4*>(out + (size_t)w * 64 + l * 4) = o4;
    }
}

// ---------------- launcher --------------------------------------------------
extern "C" void kernel_launch(void* const* d_in, const int* in_sizes, int n_in,
                              void* d_out, int out_size)
{
    const float* x   = (const float*)d_in[0];
    const int*  esrc = (const int*)d_in[1];
    const int*  edst = (const int*)d_in[2];
    const float* Wr0 = (const float*)d_in[3];
    const float* Wn0 = (const float*)d_in[4];
    const float* b0  = (const float*)d_in[5];
    const float* g0  = (const float*)d_in[6];
    const float* be0 = (const float*)d_in[7];
    const float* Wr1 = (const float*)d_in[8];
    const float* Wn1 = (const float*)d_in[9];
    const float* b1  = (const float*)d_in[10];
    const float* g1  = (const float*)d_in[11];
    const float* be1 = (const float*)d_in[12];
    const float* Wr2 = (const float*)d_in[13];
    const float* Wn2 = (const float*)d_in[14];
    const float* b2  = (const float*)d_in[15];
    float* out = (float*)d_out;

    int n = in_sizes[0] / 128;
    int E = in_sizes[1];
    if (n > MAXN) n = MAXN;
    if (E > MAXE) E = MAXE;

    int *degi, *off, *cursor, *csr;
    float *rdeg, *t2lo;
    __half *xh, *h0h, *h1h, *t2hi, *B0, *B1, *B2;
    cudaGetSymbolAddress((void**)&degi,   g_degi);
    cudaGetSymbolAddress((void**)&off,    g_off);
    cudaGetSymbolAddress((void**)&cursor, g_cursor);
    cudaGetSymbolAddress((void**)&csr,    g_csr);
    cudaGetSymbolAddress((void**)&rdeg,   g_rdeg);
    cudaGetSymbolAddress((void**)&xh,     g_xh);
    cudaGetSymbolAddress((void**)&h0h,    g_h0h);
    cudaGetSymbolAddress((void**)&h1h,    g_h1h);
    cudaGetSymbolAddress((void**)&t2lo,   g_t2lo);
    cudaGetSymbolAddress((void**)&t2hi,   g_t2hi);
    cudaGetSymbolAddress((void**)&B0,     g_Bw0h);
    cudaGetSymbolAddress((void**)&B1,     g_Bw1h);
    cudaGetSymbolAddress((void**)&B2,     g_Bw2h);

    cudaFuncSetAttribute(k_gemm_fused, cudaFuncAttributeMaxDynamicSharedMemorySize, FS_TOTAL);
    cudaFuncSetAttribute(k_gemm2,      cudaFuncAttributeMaxDynamicSharedMemorySize, S_TOTAL);

    int gb = (n + 127) / 128;
    int gw = (n + 7) / 8;
    int FB = (E + 255) / 256;

    // CSR build (degi zero-init'd on load; re-zeroed at tail for replays)
    k_count<<<(E + 255) / 256, 256>>>(edst, degi, E);                       // 0
    k_scan<<<1, 1024>>>(degi, off, cursor, rdeg, n);                        // 1
    k_fill_plus<<<FB + 320 + 1024, 256>>>(esrc, edst, cursor, csr, E, FB,   // 2
                                          Wr0, Wn0, Wr1, Wn1, Wr2, Wn2,
                                          B0, B1, B2, x, xh, (long)n * 32);

    // layer 0 (fused gather+gemm)  -> profiled at launch idx 3
    k_gemm_fused<<<gb, 256, FS_TOTAL>>>(xh, csr, off, rdeg, B0, b0, g0, be0, h0h, n);
    // layer 1
    k_gemm_fused<<<gb, 256, FS_TOTAL>>>(h0h, csr, off, rdeg, B1, b1, g1, be1, h1h, n);
    // layer 2 + final
    k_gemm2<<<gb, 256, S_TOTAL>>>(h1h, B2, t2lo, t2hi, n);
    k_agg64_final<<<gw, 256>>>(t2lo, t2hi, csr, off, rdeg, b2, out, n);

    // restore degi = 0 for the next replay
    k_zeroi<<<(n + 255) / 256, 256>>>(degi, n);
}

// round 15
// speedup vs baseline: 1.7773x; 1.7773x over previous
#include <cuda_runtime.h>
#include <cuda_fp16.h>
#include <cstdint>

#define MAXN 100000
#define MAXE 1600000
#define EPS_LN 1e-5f
#define SCAN_B 391          // ceil(100000 / 256)

typedef unsigned long long u64;
typedef unsigned int u32;

// ---------------- scratch (device globals; no allocation allowed) ----------
__device__ int    g_degi[MAXN];
__device__ int    g_off[MAXN + 1];
__device__ int    g_cursor[MAXN];
__device__ int    g_csr[MAXE];
__device__ int    g_bsum[SCAN_B];
__device__ int    g_boff[SCAN_B];
__device__ float  g_rdeg[MAXN];
__device__ __half g_xh[(size_t)MAXN * 128];
__device__ __half g_aggh[(size_t)MAXN * 128];
__device__ __half g_h0h[(size_t)MAXN * 128];
__device__ __half g_h1h[(size_t)MAXN * 128];
__device__ float  g_t2[(size_t)MAXN * 128];
__device__ __half g_Bw0h[128 * 256];   // [n][k] half weights (concat, transposed)
__device__ __half g_Bw1h[128 * 256];
__device__ __half g_Bw2h[128 * 128];

// ---------------- helpers ---------------------------------------------------
__device__ __forceinline__ uint32_t smem_u32(const void* p) {
    uint32_t a;
    asm("{ .reg .u64 t; cvta.to.shared.u64 t, %1; cvt.u32.u64 %0, t; }" : "=r"(a) : "l"(p));
    return a;
}
__device__ __forceinline__ void cp_async16(uint32_t dst, const void* src) {
    asm volatile("cp.async.ca.shared.global [%0], [%1], 16;" :: "r"(dst), "l"(src));
}
__device__ __forceinline__ void cp_commit() {
    asm volatile("cp.async.commit_group;" ::: "memory");
}
__device__ __forceinline__ void cp_wait0() {
    asm volatile("cp.async.wait_group 0;" ::: "memory");
}
__device__ __forceinline__ void mma_f16(float* c, const u32* a, u32 b0, u32 b1) {
    asm volatile(
        "mma.sync.aligned.m16n8k16.row.col.f32.f16.f16.f32 "
        "{%0,%1,%2,%3}, {%4,%5,%6,%7}, {%8,%9}, {%0,%1,%2,%3};"
        : "+f"(c[0]), "+f"(c[1]), "+f"(c[2]), "+f"(c[3])
        : "r"(a[0]), "r"(a[1]), "r"(a[2]), "r"(a[3]), "r"(b0), "r"(b1));
}
__device__ __forceinline__ void facc(float4& a, float4 v) {
    a.x += v.x; a.y += v.y; a.z += v.z; a.w += v.w;
}
__device__ __forceinline__ float4 ldg4(const float* p) {
    return __ldg(reinterpret_cast<const float4*>(p));
}
__device__ __forceinline__ void acc_h4(float4& a, uint2 p) {
    float2 lo = __half22float2(*reinterpret_cast<__half2*>(&p.x));
    float2 hi = __half22float2(*reinterpret_cast<__half2*>(&p.y));
    a.x += lo.x; a.y += lo.y; a.z += hi.x; a.w += hi.y;
}
__device__ __forceinline__ uint2 f4_to_h4(float4 v) {
    uint2 r;
    __half2 lo = __floats2half2_rn(v.x, v.y);
    __half2 hi = __floats2half2_rn(v.z, v.w);
    r.x = *reinterpret_cast<u32*>(&lo);
    r.y = *reinterpret_cast<u32*>(&hi);
    return r;
}

// ---------------- CSR build --------------------------------------------------
__global__ void k_zeroi(int* __restrict__ p, int n) {
    int i = blockIdx.x * blockDim.x + threadIdx.x;
    if (i < n) p[i] = 0;
}

__global__ void k_count(const int* __restrict__ dst, int* __restrict__ deg, int E) {
    int i = blockIdx.x * blockDim.x + threadIdx.x;
    if (i < E) atomicAdd(&deg[dst[i]], 1);
}

// hierarchical scan, stage A: per-block sums
__global__ void __launch_bounds__(256) k_scanA(
    const int* __restrict__ deg, int* __restrict__ bsum, int n)
{
    __shared__ int sb[256];
    int i = blockIdx.x * 256 + threadIdx.x;
    int v = (i < n) ? deg[i] : 0;
    sb[threadIdx.x] = v;
    __syncthreads();
    #pragma unroll
    for (int o = 128; o > 0; o >>= 1) {
        if (threadIdx.x < o) sb[threadIdx.x] += sb[threadIdx.x + o];
        __syncthreads();
    }
    if (threadIdx.x == 0) bsum[blockIdx.x] = sb[0];
}

// stage B: single-block exclusive scan of bsum -> boff, total -> off[n]
__global__ void __launch_bounds__(512) k_scanB(
    const int* __restrict__ bsum, int* __restrict__ boff,
    int* __restrict__ off, int n, int nb)
{
    __shared__ int sb[512];
    int tid = threadIdx.x;
    int v = (tid < nb) ? bsum[tid] : 0;
    sb[tid] = v;
    __syncthreads();
    for (int o = 1; o < 512; o <<= 1) {
        int t = (tid >= o) ? sb[tid - o] : 0;
        __syncthreads();
        sb[tid] += t;
        __syncthreads();
    }
    if (tid < nb) boff[tid] = sb[tid] - v;   // exclusive
    if (tid == 511) off[n] = sb[511];        // total
}

// stage C: per-block exclusive scan + apply base -> off/cursor/rdeg
__global__ void __launch_bounds__(256) k_scanC(
    const int* __restrict__ deg, const int* __restrict__ boff,
    int* __restrict__ off, int* __restrict__ cursor,
    float* __restrict__ rdeg, int n)
{
    __shared__ int sb[256];
    int tid = threadIdx.x;
    int i = blockIdx.x * 256 + tid;
    int v = (i < n) ? deg[i] : 0;
    sb[tid] = v;
    __syncthreads();
    for (int o = 1; o < 256; o <<= 1) {
        int t = (tid >= o) ? sb[tid - o] : 0;
        __syncthreads();
        sb[tid] += t;
        __syncthreads();
    }
    if (i < n) {
        int base = boff[blockIdx.x] + sb[tid] - v;   // exclusive prefix
        off[i] = base;
        cursor[i] = base;
        rdeg[i] = 1.0f / fmaxf((float)v, 1.0f);
    }
}

__global__ void k_fill(const int* __restrict__ src, const int* __restrict__ dst,
                       int* __restrict__ cursor, int* __restrict__ csr, int E)
{
    int i = blockIdx.x * blockDim.x + threadIdx.x;
    if (i < E) {
        int p = atomicAdd(&cursor[dst[i]], 1);
        csr[p] = src[i];
    }
}

// ---------------- weight prep: half, transposed [n][k] ---------------------
__global__ void k_prep_all(
    const float* __restrict__ Wr0, const float* __restrict__ Wn0,
    const float* __restrict__ Wr1, const float* __restrict__ Wn1,
    const float* __restrict__ Wr2, const float* __restrict__ Wn2,
    __half* __restrict__ B0, __half* __restrict__ B1, __half* __restrict__ B2)
{
    int b = blockIdx.x;
    int tid = threadIdx.x;
    if (b < 256) {
        const float* Wr = (b < 128) ? Wr0 : Wr1;
        const float* Wn = (b < 128) ? Wn0 : Wn1;
        __half* B = (b < 128) ? B0 : B1;
        int i = (b & 127) * 256 + tid;     // i = n*256 + k
        int nn = i >> 8, k = i & 255;
        float v = (k < 128) ? Wr[k * 128 + nn] : Wn[(k - 128) * 128 + nn];
        B[i] = __float2half_rn(v);
    } else {
        int i = (b - 256) * 256 + tid;     // i = n*128 + k
        int nn = i >> 7, k = i & 127;
        float v = (nn < 64) ? Wr2[k * 64 + nn] : Wn2[k * 64 + (nn - 64)];
        B2[i] = __float2half_rn(v);
    }
}

__global__ void k_cvt_half(const float* __restrict__ src, __half* __restrict__ dst, long n4) {
    long i = blockIdx.x * (long)blockDim.x + threadIdx.x;
    for (; i < n4; i += (long)gridDim.x * blockDim.x) {
        float4 v = reinterpret_cast<const float4*>(src)[i];
        reinterpret_cast<uint2*>(dst)[i] = f4_to_h4(v);
    }
}

// ---------------- gather-based mean aggregation (half in, half out) --------
__global__ void __launch_bounds__(256) k_agg128h(
    const __half* __restrict__ feat, const int* __restrict__ csr,
    const int* __restrict__ off, const float* __restrict__ rdeg,
    __half* __restrict__ agg, int n)
{
    int w = (blockIdx.x * 256 + threadIdx.x) >> 5;
    int lane = threadIdx.x & 31;
    if (w >= n) return;
    int s0 = off[w], s1 = off[w + 1];
    float4 a0 = make_float4(0.f, 0.f, 0.f, 0.f);
    float4 a1 = make_float4(0.f, 0.f, 0.f, 0.f);
    float4 a2 = make_float4(0.f, 0.f, 0.f, 0.f);
    float4 a3 = make_float4(0.f, 0.f, 0.f, 0.f);
    int e = s0;
    for (; e + 4 <= s1; e += 4) {
        int i0 = csr[e], i1 = csr[e + 1], i2 = csr[e + 2], i3 = csr[e + 3];
        uint2 v0 = *reinterpret_cast<const uint2*>(feat + (size_t)i0 * 128 + lane * 4);
        uint2 v1 = *reinterpret_cast<const uint2*>(feat + (size_t)i1 * 128 + lane * 4);
        uint2 v2 = *reinterpret_cast<const uint2*>(feat + (size_t)i2 * 128 + lane * 4);
        uint2 v3 = *reinterpret_cast<const uint2*>(feat + (size_t)i3 * 128 + lane * 4);
        acc_h4(a0, v0); acc_h4(a1, v1); acc_h4(a2, v2); acc_h4(a3, v3);
    }
    for (; e < s1; e++) {
        int i0 = csr[e];
        uint2 v0 = *reinterpret_cast<const uint2*>(feat + (size_t)i0 * 128 + lane * 4);
        acc_h4(a0, v0);
    }
    float r = rdeg[w];
    float4 o4;
    o4.x = ((a0.x + a1.x) + (a2.x + a3.x)) * r;
    o4.y = ((a0.y + a1.y) + (a2.y + a3.y)) * r;
    o4.z = ((a0.z + a1.z) + (a2.z + a3.z)) * r;
    o4.w = ((a0.w + a1.w) + (a2.w + a3.w)) * r;
    *reinterpret_cast<uint2*>(agg + (size_t)w * 128 + lane * 4) = f4_to_h4(o4);
}

// fused: agg of t2 cols[64,128) + log_softmax(t2[:, :64] + agg + b2) -> out
__global__ void __launch_bounds__(256) k_agg64_final(
    const float* __restrict__ t2, const int* __restrict__ csr,
    const int* __restrict__ off, const float* __restrict__ rdeg,
    const float* __restrict__ b2, float* __restrict__ out, int n)
{
    int w = (blockIdx.x * 256 + threadIdx.x) >> 5;
    int lane = threadIdx.x & 31;
    if (w >= n) return;
    int half = lane >> 4, l = lane & 15;
    int s0 = off[w], s1 = off[w + 1];
    float4 a = make_float4(0.f, 0.f, 0.f, 0.f);
    float4 b = make_float4(0.f, 0.f, 0.f, 0.f);
    int e = s0 + half;
    for (; e + 2 < s1; e += 4) {
        int i0 = csr[e], i1 = csr[e + 2];
        float4 v0 = ldg4(t2 + (size_t)i0 * 128 + 64 + l * 4);
        float4 v1 = ldg4(t2 + (size_t)i1 * 128 + 64 + l * 4);
        facc(a, v0); facc(b, v1);
    }
    if (e < s1) {
        int i0 = csr[e];
        float4 v0 = ldg4(t2 + (size_t)i0 * 128 + 64 + l * 4);
        facc(a, v0);
    }
    a.x += b.x; a.y += b.y; a.z += b.z; a.w += b.w;
    a.x += __shfl_xor_sync(0xffffffffu, a.x, 16);
    a.y += __shfl_xor_sync(0xffffffffu, a.y, 16);
    a.z += __shfl_xor_sync(0xffffffffu, a.z, 16);
    a.w += __shfl_xor_sync(0xffffffffu, a.w, 16);
    float r = rdeg[w];
    float4 tv = ldg4(t2 + (size_t)w * 128 + l * 4);
    float4 bb = *reinterpret_cast<const float4*>(b2 + l * 4);
    float v0 = tv.x + a.x * r + bb.x;
    float v1 = tv.y + a.y * r + bb.y;
    float v2 = tv.z + a.z * r + bb.z;
    float v3 = tv.w + a.w * r + bb.w;
    float m = fmaxf(fmaxf(v0, v1), fmaxf(v2, v3));
    #pragma unroll
    for (int o = 16; o > 0; o >>= 1)
        m = fmaxf(m, __shfl_xor_sync(0xffffffffu, m, o));
    float se = (half == 0) ? (expf(v0 - m) + expf(v1 - m) + expf(v2 - m) + expf(v3 - m)) : 0.f;
    #pragma unroll
    for (int o = 16; o > 0; o >>= 1)
        se += __shfl_xor_sync(0xffffffffu, se, o);
    float ls = m + logf(se);
    if (half == 0) {
        float4 o4 = make_float4(v0 - ls, v1 - ls, v2 - ls, v3 - ls);
        *reinterpret_cast<float4*>(out + (size_t)w * 64 + l * 4) = o4;
    }
}

// ---------------- fp16 mma.sync GEMM + fused bias/LN/ReLU ------------------
// CTA tile 128x128, 8 warps (4M x 2N), warp tile 32x64, BK=32 (2 k16 steps).
// __launch_bounds__(256, 3): cap regs at 85 so 3 CTAs/SM fit (24 warps).
#define S_AS0 0
#define S_AS1 10240
#define S_BS0 20480
#define S_BS1 30720
#define S_SROW 0
#define S_BIAS 67584
#define S_GAM  68096
#define S_BET  68608
#define S_MU   69120
#define S_RS   69632
#define S_TOTAL 70144

// OUTMODE: 0 = fp32 out, 1 = half out
template<int KTOT, bool DO_LN, int OUTMODE>
__global__ void __launch_bounds__(256, 3) k_gemm_h(
    const __half* __restrict__ X, const __half* __restrict__ AGG,
    const __half* __restrict__ Bw, const float* __restrict__ bias,
    const float* __restrict__ gamma, const float* __restrict__ beta,
    float* __restrict__ outf, __half* __restrict__ outh, int n)
{
    constexpr int NC = KTOT / 32;
    extern __shared__ char sm[];
    float* sbias = (float*)(sm + S_BIAS);
    float* sgam  = (float*)(sm + S_GAM);
    float* sbet  = (float*)(sm + S_BET);
    float* smu   = (float*)(sm + S_MU);
    float* srs   = (float*)(sm + S_RS);
    float* srow  = (float*)(sm + S_SROW);  // 128 x 132 floats, epilogue only

    int tid = threadIdx.x;
    int wid = tid >> 5, lane = tid & 31;
    int g = lane >> 2, t = lane & 3;
    int wm = wid & 3, wn = wid >> 2;
    int m0 = wm * 32, n0 = wn * 64;
    int base = blockIdx.x * 128;

    if (DO_LN && tid < 128) {
        sbias[tid] = __ldg(bias + tid);
        sgam[tid]  = __ldg(gamma + tid);
        sbet[tid]  = __ldg(beta + tid);
    }

    auto preA = [&](int c, int st) {
        uint32_t abase = smem_u32(sm + (st ? S_AS1 : S_AS0));
        #pragma unroll
        for (int it = 0; it < 2; it++) {
            int idx = tid + it * 256;
            int row = idx >> 2, seg = idx & 3;
            int grow = base + row;
            if (grow < n) {
                int k = c * 32 + seg * 8;
                const __half* P = (k < 128) ? (X + (size_t)grow * 128 + k)
                                            : (AGG + (size_t)grow * 128 + (k - 128));
                cp_async16(abase + (uint32_t)(row * 80 + seg * 16), P);
            }
        }
    };
    auto preB = [&](int c, int st) {
        uint32_t bbase = smem_u32(sm + (st ? S_BS1 : S_BS0));
        #pragma unroll
        for (int it = 0; it < 2; it++) {
            int idx = tid + it * 256;
            int row = idx >> 2, seg = idx & 3;
            cp_async16(bbase + (uint32_t)(row * 80 + seg * 16),
                       Bw + (size_t)row * KTOT + c * 32 + seg * 8);
        }
    };

    float acc[2][8][4];
    #pragma unroll
    for (int mt = 0; mt < 2; mt++)
        #pragma unroll
        for (int nt = 0; nt < 8; nt++)
            #pragma unroll
            for (int cc = 0; cc < 4; cc++) acc[mt][nt][cc] = 0.f;

    preA(0, 0);
    preB(0, 0);
    cp_commit();
    cp_wait0();
    __syncthreads();

    #pragma unroll 1
    for (int c = 0; c < NC; c++) {
        int st = c & 1;
        if (c + 1 < NC) {
            preA(c + 1, st ^ 1);
            preB(c + 1, st ^ 1);
            cp_commit();
        }
        {
            const char* As = sm + (st ? S_AS1 : S_AS0);
            const char* Bs = sm + (st ? S_BS1 : S_BS0);
            #pragma unroll
            for (int ks = 0; ks < 2; ks++) {
                int kb = ks * 32 + 4 * t;
                u32 af[2][4];
                #pragma unroll
                for (int mt = 0; mt < 2; mt++) {
                    int r = m0 + mt * 16 + g;
                    af[mt][0] = *(const u32*)(As + r * 80 + kb);
                    af[mt][1] = *(const u32*)(As + (r + 8) * 80 + kb);
                    af[mt][2] = *(const u32*)(As + r * 80 + kb + 16);
                    af[mt][3] = *(const u32*)(As + (r + 8) * 80 + kb + 16);
                }
                #pragma unroll
                for (int nt = 0; nt < 8; nt++) {
                    int cc = n0 + nt * 8 + g;
                    u32 b0 = *(const u32*)(Bs + cc * 80 + kb);
                    u32 b1 = *(const u32*)(Bs + cc * 80 + kb + 16);
                    mma_f16(acc[0][nt], af[0], b0, b1);
                    mma_f16(acc[1][nt], af[1], b0, b1);
                }
            }
        }
        if (c + 1 < NC) {
            cp_wait0();
            __syncthreads();
        }
    }
    __syncthreads();

    // fragments -> srow staging
    #pragma unroll
    for (int mt = 0; mt < 2; mt++) {
        int r0 = m0 + mt * 16 + g;
        #pragma unroll
        for (int nt = 0; nt < 8; nt++) {
            int col = n0 + nt * 8 + 2 * t;
            *reinterpret_cast<float2*>(&srow[r0 * 132 + col]) =
                make_float2(acc[mt][nt][0], acc[mt][nt][1]);
            *reinterpret_cast<float2*>(&srow[(r0 + 8) * 132 + col]) =
                make_float2(acc[mt][nt][2], acc[mt][nt][3]);
        }
    }
    __syncthreads();

    // per-row LN stats (thread = row)
    if (DO_LN && tid < 128) {
        float s1 = 0.f, s2 = 0.f;
        #pragma unroll
        for (int j = 0; j < 128; j += 4) {
            float4 v = *reinterpret_cast<const float4*>(&srow[tid * 132 + j]);
            v.x += sbias[j + 0]; v.y += sbias[j + 1];
            v.z += sbias[j + 2]; v.w += sbias[j + 3];
            *reinterpret_cast<float4*>(&srow[tid * 132 + j]) = v;
            s1 += (v.x + v.y) + (v.z + v.w);
            s2 += (v.x * v.x + v.y * v.y) + (v.z * v.z + v.w * v.w);
        }
        float mu = s1 * (1.0f / 128.0f);
        float var = s2 * (1.0f / 128.0f) - mu * mu;
        smu[tid] = mu;
        srs[tid] = rsqrtf(var + EPS_LN);
    }
    __syncthreads();

    // coalesced stores
    for (int r = wid; r < 128; r += 8) {
        int row = base + r;
        if (row >= n) continue;
        float4 v = *reinterpret_cast<const float4*>(&srow[r * 132 + lane * 4]);
        if (DO_LN) {
            float mu = smu[r], rs = srs[r];
            float4 gg = *reinterpret_cast<const float4*>(&sgam[lane * 4]);
            float4 ee = *reinterpret_cast<const float4*>(&sbet[lane * 4]);
            v.x = fmaxf((v.x - mu) * rs * gg.x + ee.x, 0.f);
            v.y = fmaxf((v.y - mu) * rs * gg.y + ee.y, 0.f);
            v.z = fmaxf((v.z - mu) * rs * gg.z + ee.z, 0.f);
            v.w = fmaxf((v.w - mu) * rs * gg.w + ee.w, 0.f);
        }
        if (OUTMODE == 0) {
            *reinterpret_cast<float4*>(outf + (size_t)row * 128 + lane * 4) = v;
        } else {
            *reinterpret_cast<uint2*>(outh + (size_t)row * 128 + lane * 4) = f4_to_h4(v);
        }
    }
}

// ---------------- launcher --------------------------------------------------
extern "C" void kernel_launch(void* const* d_in, const int* in_sizes, int n_in,
                              void* d_out, int out_size)
{
    const float* x   = (const float*)d_in[0];
    const int*  esrc = (const int*)d_in[1];
    const int*  edst = (const int*)d_in[2];
    const float* Wr0 = (const float*)d_in[3];
    const float* Wn0 = (const float*)d_in[4];
    const float* b0  = (const float*)d_in[5];
    const float* g0  = (const float*)d_in[6];
    const float* be0 = (const float*)d_in[7];
    const float* Wr1 = (const float*)d_in[8];
    const float* Wn1 = (const float*)d_in[9];
    const float* b1  = (const float*)d_in[10];
    const float* g1  = (const float*)d_in[11];
    const float* be1 = (const float*)d_in[12];
    const float* Wr2 = (const float*)d_in[13];
    const float* Wn2 = (const float*)d_in[14];
    const float* b2  = (const float*)d_in[15];
    float* out = (float*)d_out;

    int n = in_sizes[0] / 128;
    int E = in_sizes[1];
    if (n > MAXN) n = MAXN;
    if (E > MAXE) E = MAXE;

    int *degi, *off, *cursor, *csr, *bsum, *boff;
    float *rdeg, *t2;
    __half *xh, *aggh, *h0h, *h1h, *B0, *B1, *B2;
    cudaGetSymbolAddress((void**)&degi,   g_degi);
    cudaGetSymbolAddress((void**)&off,    g_off);
    cudaGetSymbolAddress((void**)&cursor, g_cursor);
    cudaGetSymbolAddress((void**)&csr,    g_csr);
    cudaGetSymbolAddress((void**)&bsum,   g_bsum);
    cudaGetSymbolAddress((void**)&boff,   g_boff);
    cudaGetSymbolAddress((void**)&rdeg,   g_rdeg);
    cudaGetSymbolAddress((void**)&xh,     g_xh);
    cudaGetSymbolAddress((void**)&aggh,   g_aggh);
    cudaGetSymbolAddress((void**)&h0h,    g_h0h);
    cudaGetSymbolAddress((void**)&h1h,    g_h1h);
    cudaGetSymbolAddress((void**)&t2,     g_t2);
    cudaGetSymbolAddress((void**)&B0,     g_Bw0h);
    cudaGetSymbolAddress((void**)&B1,     g_Bw1h);
    cudaGetSymbolAddress((void**)&B2,     g_Bw2h);

    cudaFuncSetAttribute(k_gemm_h<256, true, 1>,  cudaFuncAttributeMaxDynamicSharedMemorySize, S_TOTAL);
    cudaFuncSetAttribute(k_gemm_h<128, false, 0>, cudaFuncAttributeMaxDynamicSharedMemorySize, S_TOTAL);

    int gb = (n + 127) / 128;
    int gw = (n + 7) / 8;
    int nb = (n + 255) / 256;    // == SCAN_B for n = 100000

    // CSR build (parallel hierarchical scan) + weight prep + x half mirror
    k_zeroi<<<(n + 255) / 256, 256>>>(degi, n);
    k_count<<<(E + 255) / 256, 256>>>(edst, degi, E);
    k_scanA<<<nb, 256>>>(degi, bsum, n);
    k_scanB<<<1, 512>>>(bsum, boff, off, n, nb);
    k_scanC<<<nb, 256>>>(degi, boff, off, cursor, rdeg, n);
    k_fill<<<(E + 255) / 256, 256>>>(esrc, edst, cursor, csr, E);
    k_prep_all<<<320, 256>>>(Wr0, Wn0, Wr1, Wn1, Wr2, Wn2, B0, B1, B2);
    k_cvt_half<<<1024, 256>>>(x, xh, (long)n * 32);

    // layer 0
    k_agg128h<<<gw, 256>>>(xh, csr, off, rdeg, aggh, n);
    k_gemm_h<256, true, 1><<<gb, 256, S_TOTAL>>>(xh, aggh, B0, b0, g0, be0, (float*)0, h0h, n);

    // layer 1
    k_agg128h<<<gw, 256>>>(h0h, csr, off, rdeg, aggh, n);
    k_gemm_h<256, true, 1><<<gb, 256, S_TOTAL>>>(h0h, aggh, B1, b1, g1, be1, (float*)0, h1h, n);

    // layer 2: t2 = h1 @ [Wr2 | Wn2] (fp32 out); fused agg + log_softmax
    k_gemm_h<128, false, 0><<<gb, 256, S_TOTAL>>>(h1h, h1h, B2, b2, g0, be0, t2, (__half*)0, n);
    k_agg64_final<<<gw, 256>>>(t2, csr, off, rdeg, b2, out, n);
}

// round 16
// speedup vs baseline: 2.0079x; 1.1297x over previous
#include <cuda_runtime.h>
#include <cuda_fp16.h>
#include <cstdint>

#define MAXN 100000
#define MAXE 1600000
#define EPS_LN 1e-5f
#define SCAN_B 391          // ceil(100000 / 256)

typedef unsigned long long u64;
typedef unsigned int u32;

// ---------------- scratch (device globals; no allocation allowed) ----------
__device__ int    g_degi[MAXN];
__device__ int    g_off[MAXN + 1];
__device__ int    g_cursor[MAXN];
__device__ int    g_csr[MAXE + 8];     // +8: prefetch overread pad
__device__ int    g_bsum[SCAN_B];
__device__ int    g_boff[SCAN_B];
__device__ float  g_rdeg[MAXN];
__device__ __half g_xh[(size_t)MAXN * 128];
__device__ __half g_aggh[(size_t)MAXN * 128];
__device__ __half g_h0h[(size_t)MAXN * 128];
__device__ __half g_h1h[(size_t)MAXN * 128];
__device__ float  g_t2[(size_t)MAXN * 128];
__device__ __half g_Bw0h[128 * 256];   // [n][k] half weights (concat, transposed)
__device__ __half g_Bw1h[128 * 256];
__device__ __half g_Bw2h[128 * 128];

// ---------------- helpers ---------------------------------------------------
__device__ __forceinline__ uint32_t smem_u32(const void* p) {
    uint32_t a;
    asm("{ .reg .u64 t; cvta.to.shared.u64 t, %1; cvt.u32.u64 %0, t; }" : "=r"(a) : "l"(p));
    return a;
}
__device__ __forceinline__ void cp_async16(uint32_t dst, const void* src) {
    asm volatile("cp.async.ca.shared.global [%0], [%1], 16;" :: "r"(dst), "l"(src));
}
__device__ __forceinline__ void cp_commit() {
    asm volatile("cp.async.commit_group;" ::: "memory");
}
__device__ __forceinline__ void cp_wait0() {
    asm volatile("cp.async.wait_group 0;" ::: "memory");
}
__device__ __forceinline__ void mma_f16(float* c, const u32* a, u32 b0, u32 b1) {
    asm volatile(
        "mma.sync.aligned.m16n8k16.row.col.f32.f16.f16.f32 "
        "{%0,%1,%2,%3}, {%4,%5,%6,%7}, {%8,%9}, {%0,%1,%2,%3};"
        : "+f"(c[0]), "+f"(c[1]), "+f"(c[2]), "+f"(c[3])
        : "r"(a[0]), "r"(a[1]), "r"(a[2]), "r"(a[3]), "r"(b0), "r"(b1));
}
__device__ __forceinline__ void facc(float4& a, float4 v) {
    a.x += v.x; a.y += v.y; a.z += v.z; a.w += v.w;
}
__device__ __forceinline__ float4 ldg4(const float* p) {
    return __ldg(reinterpret_cast<const float4*>(p));
}
__device__ __forceinline__ __half2 h2(u32 v) {
    return *reinterpret_cast<__half2*>(&v);
}
__device__ __forceinline__ void acc_h4(float4& a, uint2 p) {
    float2 lo = __half22float2(h2(p.x));
    float2 hi = __half22float2(h2(p.y));
    a.x += lo.x; a.y += lo.y; a.z += hi.x; a.w += hi.y;
}
__device__ __forceinline__ uint2 f4_to_h4(float4 v) {
    uint2 r;
    __half2 lo = __floats2half2_rn(v.x, v.y);
    __half2 hi = __floats2half2_rn(v.z, v.w);
    r.x = *reinterpret_cast<u32*>(&lo);
    r.y = *reinterpret_cast<u32*>(&hi);
    return r;
}

// ---------------- CSR build --------------------------------------------------
__global__ void k_zeroi(int* __restrict__ p, int n) {
    int i = blockIdx.x * blockDim.x + threadIdx.x;
    if (i < n) p[i] = 0;
}

// multi-role: count + weight prep + x->half (independent roles, one launch)
__global__ void k_count_plus(
    const int* __restrict__ dst, int* __restrict__ deg, int E, int CB,
    const float* __restrict__ Wr0, const float* __restrict__ Wn0,
    const float* __restrict__ Wr1, const float* __restrict__ Wn1,
    const float* __restrict__ Wr2, const float* __restrict__ Wn2,
    __half* __restrict__ B0, __half* __restrict__ B1, __half* __restrict__ B2,
    const float* __restrict__ x, __half* __restrict__ xh, long n4)
{
    int b = blockIdx.x;
    int tid = threadIdx.x;
    if (b < CB) {
        int i = b * 256 + tid;
        if (i < E) atomicAdd(&deg[dst[i]], 1);
    } else if (b < CB + 320) {
        int bb = b - CB;
        if (bb < 256) {
            const float* Wr = (bb < 128) ? Wr0 : Wr1;
            const float* Wn = (bb < 128) ? Wn0 : Wn1;
            __half* B = (bb < 128) ? B0 : B1;
            int i = (bb & 127) * 256 + tid;     // i = n*256 + k
            int nn = i >> 8, k = i & 255;
            float v = (k < 128) ? Wr[k * 128 + nn] : Wn[(k - 128) * 128 + nn];
            B[i] = __float2half_rn(v);
        } else {
            int i = (bb - 256) * 256 + tid;     // i = n*128 + k
            int nn = i >> 7, k = i & 127;
            float v = (nn < 64) ? Wr2[k * 64 + nn] : Wn2[k * 64 + (nn - 64)];
            B2[i] = __float2half_rn(v);
        }
    } else {
        long i = (long)(b - CB - 320) * 256 + tid;
        for (; i < n4; i += 1024L * 256) {
            float4 v = reinterpret_cast<const float4*>(x)[i];
            reinterpret_cast<uint2*>(xh)[i] = f4_to_h4(v);
        }
    }
}

// hierarchical scan, stage A: per-block sums
__global__ void __launch_bounds__(256) k_scanA(
    const int* __restrict__ deg, int* __restrict__ bsum, int n)
{
    __shared__ int sb[256];
    int i = blockIdx.x * 256 + threadIdx.x;
    int v = (i < n) ? deg[i] : 0;
    sb[threadIdx.x] = v;
    __syncthreads();
    #pragma unroll
    for (int o = 128; o > 0; o >>= 1) {
        if (threadIdx.x < o) sb[threadIdx.x] += sb[threadIdx.x + o];
        __syncthreads();
    }
    if (threadIdx.x == 0) bsum[blockIdx.x] = sb[0];
}

// stage B: single-block exclusive scan of bsum -> boff, total -> off[n]
__global__ void __launch_bounds__(512) k_scanB(
    const int* __restrict__ bsum, int* __restrict__ boff,
    int* __restrict__ off, int n, int nb)
{
    __shared__ int sb[512];
    int tid = threadIdx.x;
    int v = (tid < nb) ? bsum[tid] : 0;
    sb[tid] = v;
    __syncthreads();
    for (int o = 1; o < 512; o <<= 1) {
        int t = (tid >= o) ? sb[tid - o] : 0;
        __syncthreads();
        sb[tid] += t;
        __syncthreads();
    }
    if (tid < nb) boff[tid] = sb[tid] - v;   // exclusive
    if (tid == 511) off[n] = sb[511];        // total
}

// stage C: per-block exclusive scan + apply base -> off/cursor/rdeg
__global__ void __launch_bounds__(256) k_scanC(
    const int* __restrict__ deg, const int* __restrict__ boff,
    int* __restrict__ off, int* __restrict__ cursor,
    float* __restrict__ rdeg, int n)
{
    __shared__ int sb[256];
    int tid = threadIdx.x;
    int i = blockIdx.x * 256 + tid;
    int v = (i < n) ? deg[i] : 0;
    sb[tid] = v;
    __syncthreads();
    for (int o = 1; o < 256; o <<= 1) {
        int t = (tid >= o) ? sb[tid - o] : 0;
        __syncthreads();
        sb[tid] += t;
        __syncthreads();
    }
    if (i < n) {
        int base = boff[blockIdx.x] + sb[tid] - v;   // exclusive prefix
        off[i] = base;
        cursor[i] = base;
        rdeg[i] = 1.0f / fmaxf((float)v, 1.0f);
    }
}

__global__ void k_fill(const int* __restrict__ src, const int* __restrict__ dst,
                       int* __restrict__ cursor, int* __restrict__ csr, int E)
{
    int i = blockIdx.x * blockDim.x + threadIdx.x;
    if (i < E) {
        int p = atomicAdd(&cursor[dst[i]], 1);
        csr[p] = src[i];
    }
}

// ---------------- gather mean agg: idx-prefetch + pairwise HADD2 -----------
__global__ void __launch_bounds__(256) k_agg128h(
    const __half* __restrict__ feat, const int* __restrict__ csr,
    const int* __restrict__ off, const float* __restrict__ rdeg,
    __half* __restrict__ agg, int n)
{
    int w = (blockIdx.x * 256 + threadIdx.x) >> 5;
    int lane = threadIdx.x & 31;
    if (w >= n) return;
    int s0 = off[w], s1 = off[w + 1];
    const __half* fl = feat + lane * 4;
    float4 a0 = make_float4(0.f, 0.f, 0.f, 0.f);
    float4 a1 = make_float4(0.f, 0.f, 0.f, 0.f);
    int nq = (s1 - s0) >> 2;
    int e = s0;
    int i0 = 0, i1 = 0, i2 = 0, i3 = 0;
    if (nq > 0) { i0 = csr[e]; i1 = csr[e + 1]; i2 = csr[e + 2]; i3 = csr[e + 3]; }
    for (int q = 0; q < nq; q++) {
        int c0 = i0, c1 = i1, c2 = i2, c3 = i3;
        e += 4;
        // prefetch next quad (csr padded +8; harmless overread on last iter)
        i0 = csr[e]; i1 = csr[e + 1]; i2 = csr[e + 2]; i3 = csr[e + 3];
        uint2 v0 = *reinterpret_cast<const uint2*>(fl + (size_t)c0 * 128);
        uint2 v1 = *reinterpret_cast<const uint2*>(fl + (size_t)c1 * 128);
        uint2 v2 = *reinterpret_cast<const uint2*>(fl + (size_t)c2 * 128);
        uint2 v3 = *reinterpret_cast<const uint2*>(fl + (size_t)c3 * 128);
        // pairwise half2 pre-reduction (one extra 2^-11 rounding per value)
        __half2 p0x = __hadd2(h2(v0.x), h2(v1.x));
        __half2 p0y = __hadd2(h2(v0.y), h2(v1.y));
        __half2 p1x = __hadd2(h2(v2.x), h2(v3.x));
        __half2 p1y = __hadd2(h2(v2.y), h2(v3.y));
        float2 f;
        f = __half22float2(p0x); a0.x += f.x; a0.y += f.y;
        f = __half22float2(p0y); a0.z += f.x; a0.w += f.y;
        f = __half22float2(p1x); a1.x += f.x; a1.y += f.y;
        f = __half22float2(p1y); a1.z += f.x; a1.w += f.y;
    }
    for (; e < s1; e++) {
        int c0 = csr[e];
        uint2 v0 = *reinterpret_cast<const uint2*>(fl + (size_t)c0 * 128);
        acc_h4(a0, v0);
    }
    float r = rdeg[w];
    float4 o4;
    o4.x = (a0.x + a1.x) * r;
    o4.y = (a0.y + a1.y) * r;
    o4.z = (a0.z + a1.z) * r;
    o4.w = (a0.w + a1.w) * r;
    *reinterpret_cast<uint2*>(agg + (size_t)w * 128 + lane * 4) = f4_to_h4(o4);
}

// fused: agg of t2 cols[64,128) + log_softmax(t2[:, :64] + agg + b2) -> out
__global__ void __launch_bounds__(256) k_agg64_final(
    const float* __restrict__ t2, const int* __restrict__ csr,
    const int* __restrict__ off, const float* __restrict__ rdeg,
    const float* __restrict__ b2, float* __restrict__ out, int n)
{
    int w = (blockIdx.x * 256 + threadIdx.x) >> 5;
    int lane = threadIdx.x & 31;
    if (w >= n) return;
    int half = lane >> 4, l = lane & 15;
    int s0 = off[w], s1 = off[w + 1];
    float4 a = make_float4(0.f, 0.f, 0.f, 0.f);
    float4 b = make_float4(0.f, 0.f, 0.f, 0.f);
    const float* tl = t2 + 64 + l * 4;
    int e = s0 + half;
    for (; e + 2 < s1; e += 4) {
        int i0 = csr[e], i1 = csr[e + 2];
        float4 v0 = ldg4(tl + (size_t)i0 * 128);
        float4 v1 = ldg4(tl + (size_t)i1 * 128);
        facc(a, v0); facc(b, v1);
    }
    if (e < s1) {
        int i0 = csr[e];
        float4 v0 = ldg4(tl + (size_t)i0 * 128);
        facc(a, v0);
    }
    a.x += b.x; a.y += b.y; a.z += b.z; a.w += b.w;
    a.x += __shfl_xor_sync(0xffffffffu, a.x, 16);
    a.y += __shfl_xor_sync(0xffffffffu, a.y, 16);
    a.z += __shfl_xor_sync(0xffffffffu, a.z, 16);
    a.w += __shfl_xor_sync(0xffffffffu, a.w, 16);
    float r = rdeg[w];
    float4 tv = ldg4(t2 + (size_t)w * 128 + l * 4);
    float4 bb = *reinterpret_cast<const float4*>(b2 + l * 4);
    float v0 = tv.x + a.x * r + bb.x;
    float v1 = tv.y + a.y * r + bb.y;
    float v2 = tv.z + a.z * r + bb.z;
    float v3 = tv.w + a.w * r + bb.w;
    float m = fmaxf(fmaxf(v0, v1), fmaxf(v2, v3));
    #pragma unroll
    for (int o = 16; o > 0; o >>= 1)
        m = fmaxf(m, __shfl_xor_sync(0xffffffffu, m, o));
    float se = (half == 0) ? (expf(v0 - m) + expf(v1 - m) + expf(v2 - m) + expf(v3 - m)) : 0.f;
    #pragma unroll
    for (int o = 16; o > 0; o >>= 1)
        se += __shfl_xor_sync(0xffffffffu, se, o);
    float ls = m + logf(se);
    if (half == 0) {
        float4 o4 = make_float4(v0 - ls, v1 - ls, v2 - ls, v3 - ls);
        *reinterpret_cast<float4*>(out + (size_t)w * 64 + l * 4) = o4;
    }
}

// ---------------- fp16 mma.sync GEMM + fused bias/LN/ReLU ------------------
// CTA tile 128x128, 8 warps (4M x 2N), warp tile 32x64, BK=32 (2 k16 steps).
// __launch_bounds__(256, 3): 3 CTAs/SM (24 warps).
#define S_AS0 0
#define S_AS1 10240
#define S_BS0 20480
#define S_BS1 30720
#define S_SROW 0
#define S_BIAS 67584
#define S_GAM  68096
#define S_BET  68608
#define S_MU   69120
#define S_RS   69632
#define S_TOTAL 70144

// OUTMODE: 0 = fp32 out, 1 = half out
template<int KTOT, bool DO_LN, int OUTMODE>
__global__ void __launch_bounds__(256, 3) k_gemm_h(
    const __half* __restrict__ X, const __half* __restrict__ AGG,
    const __half* __restrict__ Bw, const float* __restrict__ bias,
    const float* __restrict__ gamma, const float* __restrict__ beta,
    float* __restrict__ outf, __half* __restrict__ outh, int n)
{
    constexpr int NC = KTOT / 32;
    extern __shared__ char sm[];
    float* sbias = (float*)(sm + S_BIAS);
    float* sgam  = (float*)(sm + S_GAM);
    float* sbet  = (float*)(sm + S_BET);
    float* smu   = (float*)(sm + S_MU);
    float* srs   = (float*)(sm + S_RS);
    float* srow  = (float*)(sm + S_SROW);  // 128 x 132 floats, epilogue only

    int tid = threadIdx.x;
    int wid = tid >> 5, lane = tid & 31;
    int g = lane >> 2, t = lane & 3;
    int wm = wid & 3, wn = wid >> 2;
    int m0 = wm * 32, n0 = wn * 64;
    int base = blockIdx.x * 128;

    if (DO_LN && tid < 128) {
        sbias[tid] = __ldg(bias + tid);
        sgam[tid]  = __ldg(gamma + tid);
        sbet[tid]  = __ldg(beta + tid);
    }

    auto preA = [&](int c, int st) {
        uint32_t abase = smem_u32(sm + (st ? S_AS1 : S_AS0));
        #pragma unroll
        for (int it = 0; it < 2; it++) {
            int idx = tid + it * 256;
            int row = idx >> 2, seg = idx & 3;
            int grow = base + row;
            if (grow < n) {
                int k = c * 32 + seg * 8;
                const __half* P = (k < 128) ? (X + (size_t)grow * 128 + k)
                                            : (AGG + (size_t)grow * 128 + (k - 128));
                cp_async16(abase + (uint32_t)(row * 80 + seg * 16), P);
            }
        }
    };
    auto preB = [&](int c, int st) {
        uint32_t bbase = smem_u32(sm + (st ? S_BS1 : S_BS0));
        #pragma unroll
        for (int it = 0; it < 2; it++) {
            int idx = tid + it * 256;
            int row = idx >> 2, seg = idx & 3;
            cp_async16(bbase + (uint32_t)(row * 80 + seg * 16),
                       Bw + (size_t)row * KTOT + c * 32 + seg * 8);
        }
    };

    float acc[2][8][4];
    #pragma unroll
    for (int mt = 0; mt < 2; mt++)
        #pragma unroll
        for (int nt = 0; nt < 8; nt++)
            #pragma unroll
            for (int cc = 0; cc < 4; cc++) acc[mt][nt][cc] = 0.f;

    preA(0, 0);
    preB(0, 0);
    cp_commit();
    cp_wait0();
    __syncthreads();

    #pragma unroll 1
    for (int c = 0; c < NC; c++) {
        int st = c & 1;
        if (c + 1 < NC) {
            preA(c + 1, st ^ 1);
            preB(c + 1, st ^ 1);
            cp_commit();
        }
        {
            const char* As = sm + (st ? S_AS1 : S_AS0);
            const char* Bs = sm + (st ? S_BS1 : S_BS0);
            #pragma unroll
            for (int ks = 0; ks < 2; ks++) {
                int kb = ks * 32 + 4 * t;
                u32 af[2][4];
                #pragma unroll
                for (int mt = 0; mt < 2; mt++) {
                    int r = m0 + mt * 16 + g;
                    af[mt][0] = *(const u32*)(As + r * 80 + kb);
                    af[mt][1] = *(const u32*)(As + (r + 8) * 80 + kb);
                    af[mt][2] = *(const u32*)(As + r * 80 + kb + 16);
                    af[mt][3] = *(const u32*)(As + (r + 8) * 80 + kb + 16);
                }
                #pragma unroll
                for (int nt = 0; nt < 8; nt++) {
                    int cc = n0 + nt * 8 + g;
                    u32 b0 = *(const u32*)(Bs + cc * 80 + kb);
                    u32 b1 = *(const u32*)(Bs + cc * 80 + kb + 16);
                    mma_f16(acc[0][nt], af[0], b0, b1);
                    mma_f16(acc[1][nt], af[1], b0, b1);
                }
            }
        }
        if (c + 1 < NC) {
            cp_wait0();
            __syncthreads();
        }
    }
    __syncthreads();

    // fragments -> srow staging
    #pragma unroll
    for (int mt = 0; mt < 2; mt++) {
        int r0 = m0 + mt * 16 + g;
        #pragma unroll
        for (int nt = 0; nt < 8; nt++) {
            int col = n0 + nt * 8 + 2 * t;
            *reinterpret_cast<float2*>(&srow[r0 * 132 + col]) =
                make_float2(acc[mt][nt][0], acc[mt][nt][1]);
            *reinterpret_cast<float2*>(&srow[(r0 + 8) * 132 + col]) =
                make_float2(acc[mt][nt][2], acc[mt][nt][3]);
        }
    }
    __syncthreads();

    // per-row LN stats (thread = row)
    if (DO_LN && tid < 128) {
        float s1 = 0.f, s2 = 0.f;
        #pragma unroll
        for (int j = 0; j < 128; j += 4) {
            float4 v = *reinterpret_cast<const float4*>(&srow[tid * 132 + j]);
            v.x += sbias[j + 0]; v.y += sbias[j + 1];
            v.z += sbias[j + 2]; v.w += sbias[j + 3];
            *reinterpret_cast<float4*>(&srow[tid * 132 + j]) = v;
            s1 += (v.x + v.y) + (v.z + v.w);
            s2 += (v.x * v.x + v.y * v.y) + (v.z * v.z + v.w * v.w);
        }
        float mu = s1 * (1.0f / 128.0f);
        float var = s2 * (1.0f / 128.0f) - mu * mu;
        smu[tid] = mu;
        srs[tid] = rsqrtf(var + EPS_LN);
    }
    __syncthreads();

    // coalesced stores
    for (int r = wid; r < 128; r += 8) {
        int row = base + r;
        if (row >= n) continue;
        float4 v = *reinterpret_cast<const float4*>(&srow[r * 132 + lane * 4]);
        if (DO_LN) {
            float mu = smu[r], rs = srs[r];
            float4 gg = *reinterpret_cast<const float4*>(&sgam[lane * 4]);
            float4 ee = *reinterpret_cast<const float4*>(&sbet[lane * 4]);
            v.x = fmaxf((v.x - mu) * rs * gg.x + ee.x, 0.f);
            v.y = fmaxf((v.y - mu) * rs * gg.y + ee.y, 0.f);
            v.z = fmaxf((v.z - mu) * rs * gg.z + ee.z, 0.f);
            v.w = fmaxf((v.w - mu) * rs * gg.w + ee.w, 0.f);
        }
        if (OUTMODE == 0) {
            *reinterpret_cast<float4*>(outf + (size_t)row * 128 + lane * 4) = v;
        } else {
            *reinterpret_cast<uint2*>(outh + (size_t)row * 128 + lane * 4) = f4_to_h4(v);
        }
    }
}

// ---------------- launcher --------------------------------------------------
extern "C" void kernel_launch(void* const* d_in, const int* in_sizes, int n_in,
                              void* d_out, int out_size)
{
    const float* x   = (const float*)d_in[0];
    const int*  esrc = (const int*)d_in[1];
    const int*  edst = (const int*)d_in[2];
    const float* Wr0 = (const float*)d_in[3];
    const float* Wn0 = (const float*)d_in[4];
    const float* b0  = (const float*)d_in[5];
    const float* g0  = (const float*)d_in[6];
    const float* be0 = (const float*)d_in[7];
    const float* Wr1 = (const float*)d_in[8];
    const float* Wn1 = (const float*)d_in[9];
    const float* b1  = (const float*)d_in[10];
    const float* g1  = (const float*)d_in[11];
    const float* be1 = (const float*)d_in[12];
    const float* Wr2 = (const float*)d_in[13];
    const float* Wn2 = (const float*)d_in[14];
    const float* b2  = (const float*)d_in[15];
    float* out = (float*)d_out;

    int n = in_sizes[0] / 128;
    int E = in_sizes[1];
    if (n > MAXN) n = MAXN;
    if (E > MAXE) E = MAXE;

    int *degi, *off, *cursor, *csr, *bsum, *boff;
    float *rdeg, *t2;
    __half *xh, *aggh, *h0h, *h1h, *B0, *B1, *B2;
    cudaGetSymbolAddress((void**)&degi,   g_degi);
    cudaGetSymbolAddress((void**)&off,    g_off);
    cudaGetSymbolAddress((void**)&cursor, g_cursor);
    cudaGetSymbolAddress((void**)&csr,    g_csr);
    cudaGetSymbolAddress((void**)&bsum,   g_bsum);
    cudaGetSymbolAddress((void**)&boff,   g_boff);
    cudaGetSymbolAddress((void**)&rdeg,   g_rdeg);
    cudaGetSymbolAddress((void**)&xh,     g_xh);
    cudaGetSymbolAddress((void**)&aggh,   g_aggh);
    cudaGetSymbolAddress((void**)&h0h,    g_h0h);
    cudaGetSymbolAddress((void**)&h1h,    g_h1h);
    cudaGetSymbolAddress((void**)&t2,     g_t2);
    cudaGetSymbolAddress((void**)&B0,     g_Bw0h);
    cudaGetSymbolAddress((void**)&B1,     g_Bw1h);
    cudaGetSymbolAddress((void**)&B2,     g_Bw2h);

    cudaFuncSetAttribute(k_gemm_h<256, true, 1>,  cudaFuncAttributeMaxDynamicSharedMemorySize, S_TOTAL);
    cudaFuncSetAttribute(k_gemm_h<128, false, 0>, cudaFuncAttributeMaxDynamicSharedMemorySize, S_TOTAL);

    int gb = (n + 127) / 128;
    int gw = (n + 7) / 8;
    int nb = (n + 255) / 256;
    int CB = (E + 255) / 256;

    // CSR build (parallel scan) + fused count/prep/cvt
    k_zeroi<<<(n + 255) / 256, 256>>>(degi, n);
    k_count_plus<<<CB + 320 + 1024, 256>>>(edst, degi, E, CB,
                                           Wr0, Wn0, Wr1, Wn1, Wr2, Wn2,
                                           B0, B1, B2, x, xh, (long)n * 32);
    k_scanA<<<nb, 256>>>(degi, bsum, n);
    k_scanB<<<1, 512>>>(bsum, boff, off, n, nb);
    k_scanC<<<nb, 256>>>(degi, boff, off, cursor, rdeg, n);
    k_fill<<<(E + 255) / 256, 256>>>(esrc, edst, cursor, csr, E);

    // layer 0
    k_agg128h<<<gw, 256>>>(xh, csr, off, rdeg, aggh, n);
    k_gemm_h<256, true, 1><<<gb, 256, S_TOTAL>>>(xh, aggh, B0, b0, g0, be0, (float*)0, h0h, n);

    // layer 1
    k_agg128h<<<gw, 256>>>(h0h, csr, off, rdeg, aggh, n);
    k_gemm_h<256, true, 1><<<gb, 256, S_TOTAL>>>(h0h, aggh, B1, b1, g1, be1, (float*)0, h1h, n);

    // layer 2: t2 = h1 @ [Wr2 | Wn2] (fp32 out); fused agg + log_softmax
    k_gemm_h<128, false, 0><<<gb, 256, S_TOTAL>>>(h1h, h1h, B2, b2, g0, be0, t2, (__half*)0, n);
    k_agg64_final<<<gw, 256>>>(t2, csr, off, rdeg, b2, out, n);
}